// round 1
// baseline (speedup 1.0000x reference)
#include <cuda_runtime.h>

#define BB   1024
#define CC   3
#define HH   224
#define WW   220
#define PROW 4
#define PCOL 5
#define PP   20      // PROW*PCOL
#define HID  32
#define PH   56      // HH/PROW
#define PW   44      // WW/PCOL
#define W4   55      // WW/4 float4 per row
#define PW4  11      // PW/4 float4 per column-patch
#define NTHR 224     // one thread per image row h; covers all 3 channels

__global__ __launch_bounds__(NTHR)
void nam_fused_kernel(const float* __restrict__ x,
                      const float* __restrict__ w1,
                      const float* __restrict__ b1,
                      const float* __restrict__ w2,
                      const float* __restrict__ b2,
                      float* __restrict__ out)
{
    __shared__ float part[NTHR * PCOL];   // per-thread column-patch partial sums
    __shared__ float contribs_s[PP];

    const int b = blockIdx.x;
    const int t = threadIdx.x;            // h = t, pr = t/PH (constant per thread)

    const float4* xb = (const float4*)(x + (size_t)b * CC * HH * WW);

    float acc[PCOL] = {0.f, 0.f, 0.f, 0.f, 0.f};

    // Thread t reads row h=t of each channel: fully coalesced float4 loads.
    #pragma unroll
    for (int c = 0; c < CC; c++) {
        const float4* row = xb + (c * HH + t) * W4;
        #pragma unroll
        for (int s = 0; s < PCOL; s++) {
            float a = 0.f;
            #pragma unroll
            for (int j = 0; j < PW4; j++) {
                float4 v = row[s * PW4 + j];
                a += (v.x + v.y) + (v.z + v.w);
            }
            acc[s] += a;
        }
    }

    #pragma unroll
    for (int s = 0; s < PCOL; s++) part[t * PCOL + s] = acc[s];
    __syncthreads();

    // 20 threads: one per patch. Reduce 56 row-partials, then scalar MLP.
    if (t < PP) {
        const int pr = t / PCOL;
        const int pc = t % PCOL;
        float sum = 0.f;
        #pragma unroll 8
        for (int i = 0; i < PH; i++)
            sum += part[(pr * PH + i) * PCOL + pc];

        const float f = sum * (1.0f / (CC * PH * PW));  // mean over 7392 elems

        float o = b2[t];
        const float* w1p = w1 + t * HID;
        const float* b1p = b1 + t * HID;
        const float* w2p = w2 + t * HID;
        #pragma unroll
        for (int k = 0; k < HID; k++) {
            float h = fmaf(f, w1p[k], b1p[k]);
            h = fmaxf(h, 0.0f);
            o = fmaf(h, w2p[k], o);
        }
        out[BB + b * PP + t] = o;   // contribs section
        contribs_s[t] = o;
    }
    __syncthreads();

    if (t == 0) {
        float sc = 0.f;
        #pragma unroll
        for (int p = 0; p < PP; p++) sc += contribs_s[p];
        out[b] = sc;                // score section
    }
}

extern "C" void kernel_launch(void* const* d_in, const int* in_sizes, int n_in,
                              void* d_out, int out_size)
{
    const float* x  = (const float*)d_in[0];
    const float* w1 = (const float*)d_in[1];
    const float* b1 = (const float*)d_in[2];
    const float* w2 = (const float*)d_in[3];
    const float* b2 = (const float*)d_in[4];
    float* out = (float*)d_out;

    nam_fused_kernel<<<BB, NTHR>>>(x, w1, b1, w2, b2, out);
}

// round 2
// speedup vs baseline: 1.7140x; 1.7140x over previous
#include <cuda_runtime.h>

#define BB   1024
#define CC   3
#define HH   224
#define WW   220
#define PROW 4
#define PCOL 5
#define PP   20      // PROW*PCOL
#define HID  32
#define PH   56      // HH/PROW
#define PW   44      // WW/PCOL
#define W4   55      // WW/4 float4 per row
#define PW4  11      // PW/4 float4 per column-patch

// per-(image, patch, channel) partial sums
__device__ float g_scratch[BB * PP * CC];

// ---------------------------------------------------------------------------
// Kernel 1: pooling. grid = (BB, CC); block = (56, 8).
// Thread (tx, ty): tx = float4 column within the row (tx<55 active),
// ty = row slot; rows walked as pr (static) x 7 iterations of 8 rows.
// Consecutive tx -> consecutive 16B -> fully coalesced, every 128B line
// fully consumed (rows are 880B contiguous).
// ---------------------------------------------------------------------------
__global__ __launch_bounds__(448)
void nam_pool_kernel(const float* __restrict__ x)
{
    const int b  = blockIdx.x;
    const int c  = blockIdx.y;
    const int tx = threadIdx.x;   // 0..55 (55 idle for loads)
    const int ty = threadIdx.y;   // 0..7

    const float4* base = (const float4*)(x) + (size_t)(b * CC + c) * (HH * W4);

    float acc[PROW] = {0.f, 0.f, 0.f, 0.f};

    if (tx < W4) {
        #pragma unroll
        for (int pr = 0; pr < PROW; pr++) {
            #pragma unroll
            for (int i = 0; i < PH / 8; i++) {          // 7 iterations
                const int h = pr * PH + i * 8 + ty;
                float4 v = base[h * W4 + tx];
                acc[pr] += (v.x + v.y) + (v.z + v.w);
            }
        }
    }

    __shared__ float part[PROW][8][56];
    #pragma unroll
    for (int pr = 0; pr < PROW; pr++)
        part[pr][ty][tx] = acc[pr];                      // tx==55 stores 0
    __syncthreads();

    // 20 reducer threads: patch p = pr*5 + pc, sum over ty (8) and 11 cols.
    const int tid = ty * 56 + tx;
    if (tid < PP) {
        const int pr = tid / PCOL;
        const int pc = tid % PCOL;
        float s = 0.f;
        #pragma unroll
        for (int yy = 0; yy < 8; yy++) {
            float a = 0.f;
            #pragma unroll
            for (int k = 0; k < PW4; k++)
                a += part[pr][yy][pc * PW4 + k];
            s += a;
        }
        g_scratch[(b * PP + tid) * CC + c] = s;
    }
}

// ---------------------------------------------------------------------------
// Kernel 2: channel combine + per-patch scalar MLP + score.
// grid = BB, block = 32 (one warp).
// ---------------------------------------------------------------------------
__global__ __launch_bounds__(32)
void nam_mlp_kernel(const float* __restrict__ w1,
                    const float* __restrict__ b1,
                    const float* __restrict__ w2,
                    const float* __restrict__ b2,
                    float* __restrict__ out)
{
    const int b = blockIdx.x;
    const int t = threadIdx.x;

    float o = 0.f;
    if (t < PP) {
        const float* sp = &g_scratch[(b * PP + t) * CC];
        const float f = (sp[0] + sp[1] + sp[2]) * (1.0f / (CC * PH * PW));

        o = b2[t];
        const float* w1p = w1 + t * HID;
        const float* b1p = b1 + t * HID;
        const float* w2p = w2 + t * HID;
        #pragma unroll
        for (int k = 0; k < HID; k++) {
            float h = fmaf(f, w1p[k], b1p[k]);
            h = fmaxf(h, 0.0f);
            o = fmaf(h, w2p[k], o);
        }
        out[BB + b * PP + t] = o;    // contribs section
    }

    // warp-reduce the 20 contribs (lanes >= 20 contribute 0)
    float sc = o;
    #pragma unroll
    for (int off = 16; off > 0; off >>= 1)
        sc += __shfl_down_sync(0xFFFFFFFFu, sc, off);
    if (t == 0)
        out[b] = sc;                 // score section
}

extern "C" void kernel_launch(void* const* d_in, const int* in_sizes, int n_in,
                              void* d_out, int out_size)
{
    const float* x  = (const float*)d_in[0];
    const float* w1 = (const float*)d_in[1];
    const float* b1 = (const float*)d_in[2];
    const float* w2 = (const float*)d_in[3];
    const float* b2 = (const float*)d_in[4];
    float* out = (float*)d_out;

    dim3 grid1(BB, CC);
    dim3 blk1(56, 8);
    nam_pool_kernel<<<grid1, blk1>>>(x);
    nam_mlp_kernel<<<BB, 32>>>(w1, b1, w2, b2, out);
}

// round 3
// speedup vs baseline: 1.7891x; 1.0438x over previous
#include <cuda_runtime.h>

#define BB   1024
#define CC   3
#define PROW 4
#define PCOL 5
#define PP   20      // PROW*PCOL
#define HID  32
#define HH   224
#define WW   220
#define PH   56      // HH/PROW
#define PW   44      // WW/PCOL
#define W4   55      // WW/4 float4 per row
#define PW4  11      // PW/4 float4 per column-patch

// ---------------------------------------------------------------------------
// Fused kernel: grid = BB, block = (56, 8). One block per image.
// Thread (tx, ty): tx = float4 column within a row (tx<55 active), ty = row
// slot. Loops over 3 channels x 4 row-patches x 7 row-groups with fully
// coalesced float4 loads (consecutive tx -> consecutive 16B; every 128B line
// fully consumed). Channel sum folded into registers, so no inter-block
// combine / scratch / second kernel is needed.
// ---------------------------------------------------------------------------
__global__ __launch_bounds__(448)
void nam_fused_kernel(const float* __restrict__ x,
                      const float* __restrict__ w1,
                      const float* __restrict__ b1,
                      const float* __restrict__ w2,
                      const float* __restrict__ b2,
                      float* __restrict__ out)
{
    const int b  = blockIdx.x;
    const int tx = threadIdx.x;   // 0..55
    const int ty = threadIdx.y;   // 0..7

    const float4* base = (const float4*)(x) + (size_t)b * (CC * HH * W4);

    float acc[PROW] = {0.f, 0.f, 0.f, 0.f};

    if (tx < W4) {
        #pragma unroll
        for (int c = 0; c < CC; c++) {
            const float4* cb = base + c * (HH * W4);
            #pragma unroll
            for (int pr = 0; pr < PROW; pr++) {
                #pragma unroll
                for (int i = 0; i < PH / 8; i++) {      // 7 row-groups
                    const int h = pr * PH + i * 8 + ty;
                    float4 v = cb[h * W4 + tx];
                    acc[pr] += (v.x + v.y) + (v.z + v.w);
                }
            }
        }
    }

    __shared__ float part[PROW][8][56];
    #pragma unroll
    for (int pr = 0; pr < PROW; pr++)
        part[pr][ty][tx] = acc[pr];                      // tx==55 stores 0
    __syncthreads();

    // Warp 0, lanes 0..19: patch p = pr*5 + pc. Reduce 8x11 partials, MLP.
    const int tid = ty * 56 + tx;
    if (tid < 32) {
        float o = 0.f;
        if (tid < PP) {
            const int pr = tid / PCOL;
            const int pc = tid % PCOL;
            float s = 0.f;
            #pragma unroll
            for (int yy = 0; yy < 8; yy++) {
                float a = 0.f;
                #pragma unroll
                for (int k = 0; k < PW4; k++)
                    a += part[pr][yy][pc * PW4 + k];
                s += a;
            }
            const float f = s * (1.0f / (CC * PH * PW)); // mean over 7392 elems

            o = b2[tid];
            const float* w1p = w1 + tid * HID;
            const float* b1p = b1 + tid * HID;
            const float* w2p = w2 + tid * HID;
            #pragma unroll
            for (int k = 0; k < HID; k++) {
                float h = fmaf(f, w1p[k], b1p[k]);
                h = fmaxf(h, 0.0f);
                o = fmaf(h, w2p[k], o);
            }
            out[BB + b * PP + tid] = o;                  // contribs section
        }
        // score = sum of 20 contribs (lanes >= 20 contribute 0)
        float sc = o;
        #pragma unroll
        for (int off = 16; off > 0; off >>= 1)
            sc += __shfl_down_sync(0xFFFFFFFFu, sc, off);
        if (tid == 0)
            out[b] = sc;                                 // score section
    }
}

extern "C" void kernel_launch(void* const* d_in, const int* in_sizes, int n_in,
                              void* d_out, int out_size)
{
    const float* x  = (const float*)d_in[0];
    const float* w1 = (const float*)d_in[1];
    const float* b1 = (const float*)d_in[2];
    const float* w2 = (const float*)d_in[3];
    const float* b2 = (const float*)d_in[4];
    float* out = (float*)d_out;

    nam_fused_kernel<<<BB, dim3(56, 8)>>>(x, w1, b1, w2, b2, out);
}